// round 1
// baseline (speedup 1.0000x reference)
#include <cuda_runtime.h>
#include <cuda_bf16.h>
#include <cstdint>

#define DIM 256
#define NMOD 5
#define NROWS 16384
#define TB 64

#define TPITCH 268   // a_s pitch (floats)
#define APITCH 264   // A_s pitch (bf16)
#define BPITCH 72    // B_s pitch (bf16)

// Fused per-branch matrices M_n = Wo_n @ Wv_n (bf16) and c_n = Wo_n @ bv_n + bo_n (fp32)
__device__ __align__(16) __nv_bfloat16 g_M[NMOD][DIM * DIM];
__device__ float g_c[NMOD][DIM];

// shared memory layout for main kernel
constexpr int SM_Q  = 0;                       // q tile fp32: 64*256*4     = 65536
constexpr int SM_A  = SM_Q + TB * DIM * 4;     // a tile fp32: 64*268*4     = 68608
constexpr int SM_AT = SM_A + TB * TPITCH * 4;  // A bf16:      64*264*2     = 33792
constexpr int SM_B  = SM_AT + TB * APITCH * 2; // B bf16:      256*72*2     = 36864
constexpr int SM_G  = SM_B + DIM * BPITCH * 2; // gates:       64*8*4       = 2048
constexpr int SMEM_TOTAL = SM_G + TB * 8 * 4;  // = 206848 bytes

// ------------------------------------------------------------------
// kernel 1: M_n = Wo_n @ Wv_n   (5 small 256x256x256 GEMMs, fp32 -> bf16)
// grid (8,8,5), block (16,16); 32x32 tile, 2x2 per thread
// ------------------------------------------------------------------
__global__ void fuse_weights_kernel(const float* __restrict__ sWi, const float* __restrict__ sWo,
                                    const float* __restrict__ cWi, const float* __restrict__ cWo) {
    int n = blockIdx.z;
    const float* Wo = (n == 0) ? sWo : cWo + (size_t)(n - 1) * DIM * DIM;
    const float* Wv = (n == 0) ? sWi + 2 * DIM * DIM
                               : cWi + (size_t)(n - 1) * 3 * DIM * DIM + 2 * DIM * DIM;
    __shared__ float As[32][33];
    __shared__ float Bs[32][33];
    int tx = threadIdx.x, ty = threadIdx.y;
    int t = ty * 16 + tx;
    int d0 = blockIdx.y * 32, k0 = blockIdx.x * 32;
    float c00 = 0.f, c01 = 0.f, c10 = 0.f, c11 = 0.f;
    for (int jc = 0; jc < DIM; jc += 32) {
#pragma unroll
        for (int i = 0; i < 4; i++) {
            int e = t + i * 256, rr = e >> 5, cc = e & 31;
            As[rr][cc] = Wo[(size_t)(d0 + rr) * DIM + jc + cc];
            Bs[rr][cc] = Wv[(size_t)(jc + rr) * DIM + k0 + cc];
        }
        __syncthreads();
#pragma unroll
        for (int jj = 0; jj < 32; jj++) {
            float a0 = As[ty * 2][jj], a1 = As[ty * 2 + 1][jj];
            float b0 = Bs[jj][tx * 2], b1 = Bs[jj][tx * 2 + 1];
            c00 += a0 * b0; c01 += a0 * b1; c10 += a1 * b0; c11 += a1 * b1;
        }
        __syncthreads();
    }
    g_M[n][(d0 + ty * 2) * DIM + k0 + tx * 2]         = __float2bfloat16(c00);
    g_M[n][(d0 + ty * 2) * DIM + k0 + tx * 2 + 1]     = __float2bfloat16(c01);
    g_M[n][(d0 + ty * 2 + 1) * DIM + k0 + tx * 2]     = __float2bfloat16(c10);
    g_M[n][(d0 + ty * 2 + 1) * DIM + k0 + tx * 2 + 1] = __float2bfloat16(c11);
}

// ------------------------------------------------------------------
// kernel 2: c_n = Wo_n @ bv_n + bo_n   (grid 5, block 256)
// ------------------------------------------------------------------
__global__ void fuse_bias_kernel(const float* __restrict__ sWo, const float* __restrict__ sbi,
                                 const float* __restrict__ sbo, const float* __restrict__ cWo,
                                 const float* __restrict__ cbi, const float* __restrict__ cbo) {
    int n = blockIdx.x;
    const float* Wo = (n == 0) ? sWo : cWo + (size_t)(n - 1) * DIM * DIM;
    const float* bi = (n == 0) ? sbi + 2 * DIM : cbi + (size_t)(n - 1) * 3 * DIM + 2 * DIM;
    const float* bo = (n == 0) ? sbo : cbo + (size_t)(n - 1) * DIM;
    __shared__ float bs[DIM];
    int t = threadIdx.x;
    bs[t] = bi[t];
    __syncthreads();
    float s0 = 0.f, s1 = 0.f, s2 = 0.f, s3 = 0.f;
#pragma unroll 4
    for (int j = 0; j < DIM; j += 4) {
        s0 += Wo[(size_t)t * DIM + j + 0] * bs[j + 0];
        s1 += Wo[(size_t)t * DIM + j + 1] * bs[j + 1];
        s2 += Wo[(size_t)t * DIM + j + 2] * bs[j + 2];
        s3 += Wo[(size_t)t * DIM + j + 3] * bs[j + 3];
    }
    g_c[n][t] = (s0 + s1) + (s2 + s3) + bo[t];
}

// ------------------------------------------------------------------
// MMA helpers (legacy bf16 mma.sync + ldmatrix)
// ------------------------------------------------------------------
__device__ __forceinline__ void ldsm_x4(uint32_t* r, const void* p) {
    uint32_t addr = (uint32_t)__cvta_generic_to_shared(p);
    asm volatile("ldmatrix.sync.aligned.m8n8.x4.shared.b16 {%0,%1,%2,%3}, [%4];"
                 : "=r"(r[0]), "=r"(r[1]), "=r"(r[2]), "=r"(r[3]) : "r"(addr));
}

__device__ __forceinline__ void mma16816(float* d, const uint32_t* a, const uint32_t* b) {
    asm volatile("mma.sync.aligned.m16n8k16.row.col.f32.bf16.bf16.f32 "
                 "{%0,%1,%2,%3},{%4,%5,%6,%7},{%8,%9},{%0,%1,%2,%3};"
                 : "+f"(d[0]), "+f"(d[1]), "+f"(d[2]), "+f"(d[3])
                 : "r"(a[0]), "r"(a[1]), "r"(a[2]), "r"(a[3]), "r"(b[0]), "r"(b[1]));
}

__device__ __forceinline__ float warp_sum(float v) {
#pragma unroll
    for (int o = 16; o; o >>= 1) v += __shfl_xor_sync(0xffffffffu, v, o);
    return v;
}

// ------------------------------------------------------------------
// main fused kernel: 64 rows/CTA, 256 threads (8 warps)
// warp grid 2(M) x 4(N): warp tile 32x64; mma m16n8k16 bf16
// ------------------------------------------------------------------
__global__ __launch_bounds__(256, 1)
void fused_main_kernel(const float* __restrict__ x,
                       const float* __restrict__ cross_ln_g, const float* __restrict__ cross_ln_b,
                       const float* __restrict__ gate_ln_g, const float* __restrict__ gate_ln_b,
                       const float* __restrict__ gate_W, const float* __restrict__ gate_b,
                       const float* __restrict__ final_ln_g, const float* __restrict__ final_ln_b,
                       const int* __restrict__ modal_idx, float* __restrict__ out) {
    extern __shared__ char smraw[];
    float* q_s = (float*)(smraw + SM_Q);                 // [64][256]
    float* a_s = (float*)(smraw + SM_A);                 // [64][TPITCH]
    __nv_bfloat16* A_s = (__nv_bfloat16*)(smraw + SM_AT);// [64][APITCH]
    __nv_bfloat16* B_s = (__nv_bfloat16*)(smraw + SM_B); // [256][BPITCH]
    float* gates_s = (float*)(smraw + SM_G);             // [64][5] (padded)

    const int tid = threadIdx.x;
    const int w = tid >> 5, l = tid & 31;
    const int wm = w & 1, wn = w >> 1;
    const int mi = *modal_idx;
    const int r0 = blockIdx.x * TB;

    // stash gate constants in a_s (free right now): gate_W[1280], gate_ln_g[256], gate_ln_b[256]
    float* w_s = a_s;
    for (int i = tid; i < 1792; i += 256)
        w_s[i] = (i < 1280) ? gate_W[i] : (i < 1536 ? gate_ln_g[i - 1280] : gate_ln_b[i - 1536]);

    // load q tile (fp32)
#pragma unroll
    for (int i = 0; i < 16; i++) {
        int e = tid + i * 256, r = e >> 6, s4 = (e & 63) << 2;
        *(float4*)(q_s + r * 256 + s4) =
            *(const float4*)(x + (size_t)(r0 + r) * (NMOD * DIM) + mi * DIM + s4);
    }
    __syncthreads();

    // ---- gates: softmax(LN(q) @ gate_W^T + gate_b) ----
    float gb[5];
#pragma unroll
    for (int n = 0; n < 5; n++) gb[n] = gate_b[n];
#pragma unroll 1
    for (int ri = 0; ri < 8; ri++) {
        int r = w * 8 + ri;
        float qv[8], sum = 0.f, sq = 0.f;
#pragma unroll
        for (int j = 0; j < 8; j++) {
            qv[j] = q_s[r * 256 + l + 32 * j];
            sum += qv[j]; sq += qv[j] * qv[j];
        }
        sum = warp_sum(sum); sq = warp_sum(sq);
        float m = sum * (1.f / DIM);
        float rs = rsqrtf(fmaxf(sq * (1.f / DIM) - m * m, 0.f) + 1e-5f);
        float lnv[8];
#pragma unroll
        for (int j = 0; j < 8; j++) {
            int c = l + 32 * j;
            lnv[j] = (qv[j] - m) * rs * w_s[1280 + c] + w_s[1536 + c];
        }
        float lg[5];
#pragma unroll
        for (int n = 0; n < 5; n++) {
            float s = 0.f;
#pragma unroll
            for (int j = 0; j < 8; j++) s += lnv[j] * w_s[n * DIM + l + 32 * j];
            s = warp_sum(s);
            lg[n] = s + gb[n];
        }
        float mx = lg[0];
#pragma unroll
        for (int n = 1; n < 5; n++) mx = fmaxf(mx, lg[n]);
        float es = 0.f;
#pragma unroll
        for (int n = 0; n < 5; n++) { lg[n] = expf(lg[n] - mx); es += lg[n]; }
        if (l == 0) {
            float inv = 1.f / es;
#pragma unroll
            for (int n = 0; n < 5; n++) gates_s[r * 5 + n] = lg[n] * inv;
        }
    }
    // (visibility of gates_s/w_s handled by the syncthreads inside the branch loop)

    float acc[8][8];  // running gated combination, this thread's (row,col) slots

#pragma unroll 1
    for (int n = 0; n < NMOD; n++) {
        // branch input modality: self uses mi; cross n uses other_idx[n-1]
        const int mod = (n == 0) ? mi : (((n - 1) < mi) ? (n - 1) : n);

        // load A tile (bf16)
        if (n == 0) {
#pragma unroll
            for (int i = 0; i < 16; i++) {
                int e = tid + i * 256, r = e >> 6, s4 = (e & 63) << 2;
                const float4 v = *(const float4*)(q_s + r * 256 + s4);
                __nv_bfloat16* dst = A_s + r * APITCH + s4;
                dst[0] = __float2bfloat16(v.x); dst[1] = __float2bfloat16(v.y);
                dst[2] = __float2bfloat16(v.z); dst[3] = __float2bfloat16(v.w);
            }
        } else {
#pragma unroll
            for (int i = 0; i < 16; i++) {
                int e = tid + i * 256, r = e >> 6, s4 = (e & 63) << 2;
                const float4 v = *(const float4*)(x + (size_t)(r0 + r) * (NMOD * DIM) + mod * DIM + s4);
                __nv_bfloat16* dst = A_s + r * APITCH + s4;
                dst[0] = __float2bfloat16(v.x); dst[1] = __float2bfloat16(v.y);
                dst[2] = __float2bfloat16(v.z); dst[3] = __float2bfloat16(v.w);
            }
        }

        const __nv_bfloat16* Bg = g_M[n];
        float cf[2][8][4];
#pragma unroll
        for (int mt = 0; mt < 2; mt++)
#pragma unroll
            for (int nt = 0; nt < 8; nt++)
#pragma unroll
                for (int i = 0; i < 4; i++) cf[mt][nt][i] = 0.f;

#pragma unroll 1
        for (int kc = 0; kc < 4; kc++) {
            __syncthreads();   // prev consumers of B_s done (and A_s/gates visible on kc==0)
            // load B chunk: all 256 rows (N), 64 K columns
#pragma unroll
            for (int i = 0; i < 8; i++) {
                int e = tid + i * 256, row = e >> 3, seg = e & 7;
                *(uint4*)(B_s + row * BPITCH + seg * 8) =
                    *(const uint4*)(Bg + row * DIM + kc * 64 + seg * 8);
            }
            __syncthreads();
#pragma unroll
            for (int ks = 0; ks < 4; ks++) {
                uint32_t af[2][4];
#pragma unroll
                for (int mt = 0; mt < 2; mt++) {
                    int row = wm * 32 + mt * 16 + (l & 7) + ((l >> 3) & 1) * 8;
                    int col = kc * 64 + ks * 16 + (l >> 4) * 8;
                    ldsm_x4(af[mt], A_s + row * APITCH + col);
                }
                uint32_t bfr[8][2];
#pragma unroll
                for (int np = 0; np < 4; np++) {
                    int row = wn * 64 + np * 16 + (l & 7) + (l >> 4) * 8;
                    int col = ks * 16 + ((l >> 3) & 1) * 8;
                    uint32_t r4[4];
                    ldsm_x4(r4, B_s + row * BPITCH + col);
                    bfr[2 * np][0] = r4[0]; bfr[2 * np][1] = r4[1];
                    bfr[2 * np + 1][0] = r4[2]; bfr[2 * np + 1][1] = r4[3];
                }
#pragma unroll
                for (int mt = 0; mt < 2; mt++)
#pragma unroll
                    for (int nt = 0; nt < 8; nt++)
                        mma16816(cf[mt][nt], af[mt], bfr[nt]);
            }
        }
        __syncthreads();   // GEMM done; previous epilogue's a_s reads done

        // stage accum tile to smem for row-wise LN
#pragma unroll
        for (int mt = 0; mt < 2; mt++)
#pragma unroll
            for (int nt = 0; nt < 8; nt++) {
                int r = wm * 32 + mt * 16 + (l >> 2);
                int c = wn * 64 + nt * 8 + 2 * (l & 3);
                *(float2*)(a_s + r * TPITCH + c)        = make_float2(cf[mt][nt][0], cf[mt][nt][1]);
                *(float2*)(a_s + (r + 8) * TPITCH + c)  = make_float2(cf[mt][nt][2], cf[mt][nt][3]);
            }
        __syncthreads();

        // ---- epilogue: gated accumulate (warp w owns rows 8w..8w+7) ----
        const float* cv = g_c[n];
        float cvv[8];
#pragma unroll
        for (int j = 0; j < 8; j++) cvv[j] = cv[l + 32 * j];

        if (n == 0) {
#pragma unroll
            for (int ri = 0; ri < 8; ri++) {
                int r = w * 8 + ri;
                float g0 = gates_s[r * 5 + 0];
#pragma unroll
                for (int j = 0; j < 8; j++)
                    acc[ri][j] = g0 * (a_s[r * TPITCH + l + 32 * j] + cvv[j]);
            }
        } else {
            const float* lng = cross_ln_g + (n - 1) * DIM;
            const float* lnb = cross_ln_b + (n - 1) * DIM;
            float gm[8], bt[8];
#pragma unroll
            for (int j = 0; j < 8; j++) { gm[j] = lng[l + 32 * j]; bt[j] = lnb[l + 32 * j]; }
#pragma unroll 1
            for (int ri = 0; ri < 8; ri++) {
                int r = w * 8 + ri;
                float gn = gates_s[r * 5 + n];
                float tv[8], sum = 0.f, sq = 0.f;
#pragma unroll
                for (int j = 0; j < 8; j++) {
                    tv[j] = q_s[r * DIM + l + 32 * j] + a_s[r * TPITCH + l + 32 * j] + cvv[j];
                    sum += tv[j]; sq += tv[j] * tv[j];
                }
                sum = warp_sum(sum); sq = warp_sum(sq);
                float m = sum * (1.f / DIM);
                float rs = rsqrtf(fmaxf(sq * (1.f / DIM) - m * m, 0.f) + 1e-5f);
#pragma unroll
                for (int j = 0; j < 8; j++)
                    acc[ri][j] += gn * ((tv[j] - m) * rs * gm[j] + bt[j]);
            }
        }
    }

    // ---- final LN(q + combined) and store ----
    float fg[8], fb[8];
#pragma unroll
    for (int j = 0; j < 8; j++) { fg[j] = final_ln_g[l + 32 * j]; fb[j] = final_ln_b[l + 32 * j]; }
#pragma unroll 1
    for (int ri = 0; ri < 8; ri++) {
        int r = w * 8 + ri;
        float tv[8], sum = 0.f, sq = 0.f;
#pragma unroll
        for (int j = 0; j < 8; j++) {
            tv[j] = q_s[r * DIM + l + 32 * j] + acc[ri][j];
            sum += tv[j]; sq += tv[j] * tv[j];
        }
        sum = warp_sum(sum); sq = warp_sum(sq);
        float m = sum * (1.f / DIM);
        float rs = rsqrtf(fmaxf(sq * (1.f / DIM) - m * m, 0.f) + 1e-5f);
#pragma unroll
        for (int j = 0; j < 8; j++)
            out[(size_t)(r0 + r) * DIM + l + 32 * j] = (tv[j] - m) * rs * fg[j] + fb[j];
    }
}

// ------------------------------------------------------------------
extern "C" void kernel_launch(void* const* d_in, const int* in_sizes, int n_in,
                              void* d_out, int out_size) {
    (void)in_sizes; (void)n_in; (void)out_size;
    const float* x          = (const float*)d_in[0];
    const float* self_Wi    = (const float*)d_in[1];
    const float* self_bi    = (const float*)d_in[2];
    const float* self_Wo    = (const float*)d_in[3];
    const float* self_bo    = (const float*)d_in[4];
    const float* cross_Wi   = (const float*)d_in[5];
    const float* cross_bi   = (const float*)d_in[6];
    const float* cross_Wo   = (const float*)d_in[7];
    const float* cross_bo   = (const float*)d_in[8];
    const float* cross_ln_g = (const float*)d_in[9];
    const float* cross_ln_b = (const float*)d_in[10];
    const float* gate_ln_g  = (const float*)d_in[11];
    const float* gate_ln_b  = (const float*)d_in[12];
    const float* gate_W     = (const float*)d_in[13];
    const float* gate_b     = (const float*)d_in[14];
    const float* final_ln_g = (const float*)d_in[15];
    const float* final_ln_b = (const float*)d_in[16];
    const int*   modal_idx  = (const int*)d_in[17];
    float* out = (float*)d_out;

    cudaFuncSetAttribute(fused_main_kernel,
                         cudaFuncAttributeMaxDynamicSharedMemorySize, SMEM_TOTAL);

    fuse_weights_kernel<<<dim3(8, 8, 5), dim3(16, 16)>>>(self_Wi, self_Wo, cross_Wi, cross_Wo);
    fuse_bias_kernel<<<5, 256>>>(self_Wo, self_bi, self_bo, cross_Wo, cross_bi, cross_bo);
    fused_main_kernel<<<NROWS / TB, 256, SMEM_TOTAL>>>(
        x, cross_ln_g, cross_ln_b, gate_ln_g, gate_ln_b,
        gate_W, gate_b, final_ln_g, final_ln_b, modal_idx, out);
}

// round 2
// speedup vs baseline: 1.7380x; 1.7380x over previous
#include <cuda_runtime.h>
#include <cuda_bf16.h>
#include <cstdint>

#define DIM 256
#define NMOD 5
#define NROWS 16384
#define TB 64

#define QPITCH 264   // q_s pitch (floats)
#define APITCH 264   // A_s pitch (bf16)
#define BPITCH 72    // B_s pitch (bf16)

// Fused per-branch matrices M_n = Wo_n @ Wv_n (bf16) and c_n = Wo_n @ bv_n + bo_n (fp32)
__device__ __align__(16) __nv_bfloat16 g_M[NMOD][DIM * DIM];
__device__ float g_c[NMOD][DIM];

// ---------------- shared memory layout (main kernel) ----------------
constexpr int SM_Q   = 0;                            // 64*264*4   = 67584
constexpr int SM_AT  = SM_Q + TB * QPITCH * 4;       // 64*264*2   = 33792
constexpr int SM_B   = SM_AT + TB * APITCH * 2;      // 2*256*72*2 = 73728
constexpr int SM_GW  = SM_B + 2 * DIM * BPITCH * 2;  // 1792*4     = 7168
constexpr int SM_GA  = SM_GW + 1792 * 4;             // 64*8*4     = 2048
constexpr int SM_RED = SM_GA + TB * 8 * 4;           // 64*8*4     = 2048
constexpr int SM_ST  = SM_RED + TB * 8 * 4;          // 64*2*4     = 512
constexpr int SMEM_TOTAL = SM_ST + TB * 2 * 4;       // = 186880

// ---------------- helpers ----------------
__device__ __forceinline__ void ldsm_x4(uint32_t* r, const void* p) {
    uint32_t addr = (uint32_t)__cvta_generic_to_shared(p);
    asm volatile("ldmatrix.sync.aligned.m8n8.x4.shared.b16 {%0,%1,%2,%3}, [%4];"
                 : "=r"(r[0]), "=r"(r[1]), "=r"(r[2]), "=r"(r[3]) : "r"(addr));
}

__device__ __forceinline__ void mma16816(float* d, const uint32_t* a, const uint32_t* b) {
    asm volatile("mma.sync.aligned.m16n8k16.row.col.f32.bf16.bf16.f32 "
                 "{%0,%1,%2,%3},{%4,%5,%6,%7},{%8,%9},{%0,%1,%2,%3};"
                 : "+f"(d[0]), "+f"(d[1]), "+f"(d[2]), "+f"(d[3])
                 : "r"(a[0]), "r"(a[1]), "r"(a[2]), "r"(a[3]), "r"(b[0]), "r"(b[1]));
}

__device__ __forceinline__ float warp_sum(float v) {
#pragma unroll
    for (int o = 16; o; o >>= 1) v += __shfl_xor_sync(0xffffffffu, v, o);
    return v;
}

__device__ __forceinline__ void cp_async16(void* smem, const void* g) {
    uint32_t s = (uint32_t)__cvta_generic_to_shared(smem);
    asm volatile("cp.async.cg.shared.global [%0], [%1], 16;\n" :: "r"(s), "l"(g));
}
__device__ __forceinline__ void cp_commit() { asm volatile("cp.async.commit_group;\n"); }
__device__ __forceinline__ void cp_wait_all() { asm volatile("cp.async.wait_group 0;\n"); }

// ------------------------------------------------------------------
// prologue: M_n = Wo_n @ Wv_n (bf16 mma) and c_n = Wo_n @ bv_n + bo_n
// grid (4, 5): bx = 64-row d-block, by = n.  256 threads, 8 warps (2x4).
// ------------------------------------------------------------------
__global__ __launch_bounds__(256, 1)
void fuse_weights_kernel(const float* __restrict__ sWi, const float* __restrict__ sbi,
                         const float* __restrict__ sWo, const float* __restrict__ sbo,
                         const float* __restrict__ cWi, const float* __restrict__ cbi,
                         const float* __restrict__ cWo, const float* __restrict__ cbo) {
    extern __shared__ char sm[];
    __nv_bfloat16* A_s = (__nv_bfloat16*)sm;                 // [64][APITCH]
    __nv_bfloat16* B_s = (__nv_bfloat16*)(sm + 33792);       // [256][BPITCH]
    float* bv_s = (float*)(sm + 33792 + 36864);              // [256]
    float* bred = (float*)B_s;                                // reuse after GEMM

    const int n = blockIdx.y, bx = blockIdx.x;
    const float* Wo = (n == 0) ? sWo : cWo + (size_t)(n - 1) * DIM * DIM;
    const float* Wv = (n == 0) ? sWi + 2 * DIM * DIM
                               : cWi + (size_t)(n - 1) * 3 * DIM * DIM + 2 * DIM * DIM;
    const float* bv = (n == 0) ? sbi + 2 * DIM : cbi + (size_t)(n - 1) * 3 * DIM + 2 * DIM;
    const float* bo = (n == 0) ? sbo : cbo + (size_t)(n - 1) * DIM;

    const int tid = threadIdx.x;
    const int w = tid >> 5, l = tid & 31;
    const int wm = w & 1, wn = w >> 1;
    const int lq = l >> 2, lr = l & 3;

    bv_s[tid] = bv[tid];

    // A tile: Wo rows bx*64..+63 -> bf16
#pragma unroll
    for (int i = 0; i < 16; i++) {
        int e = tid + i * 256, r = e >> 6, c4 = (e & 63) << 2;
        float4 v = *(const float4*)(Wo + (size_t)(bx * 64 + r) * DIM + c4);
        __nv_bfloat16* dst = A_s + r * APITCH + c4;
        *(__nv_bfloat162*)(dst)     = __floats2bfloat162_rn(v.x, v.y);
        *(__nv_bfloat162*)(dst + 2) = __floats2bfloat162_rn(v.z, v.w);
    }

    float cf[2][8][4];
#pragma unroll
    for (int mt = 0; mt < 2; mt++)
#pragma unroll
        for (int nt = 0; nt < 8; nt++)
#pragma unroll
            for (int i = 0; i < 4; i++) cf[mt][nt][i] = 0.f;

#pragma unroll 1
    for (int kc = 0; kc < 4; kc++) {
        __syncthreads();   // A_s/bv_s visible (kc==0), prev mma done (kc>0)
        // B_s[k 0..255][j' 0..63] = Wv[jc + j'][k]  (transposed load, coalesced reads)
        int jc = kc * 64;
#pragma unroll
        for (int i = 0; i < 16; i++) {
            int e = tid + i * 256;
            int k = e & 255, j4 = (e >> 8) << 2;
            float v0 = Wv[(size_t)(jc + j4 + 0) * DIM + k];
            float v1 = Wv[(size_t)(jc + j4 + 1) * DIM + k];
            float v2 = Wv[(size_t)(jc + j4 + 2) * DIM + k];
            float v3 = Wv[(size_t)(jc + j4 + 3) * DIM + k];
            __nv_bfloat16* dst = B_s + k * BPITCH + j4;
            *(__nv_bfloat162*)(dst)     = __floats2bfloat162_rn(v0, v1);
            *(__nv_bfloat162*)(dst + 2) = __floats2bfloat162_rn(v2, v3);
        }
        __syncthreads();
#pragma unroll
        for (int ks = 0; ks < 4; ks++) {
            uint32_t af[2][4];
#pragma unroll
            for (int mt = 0; mt < 2; mt++) {
                int row = wm * 32 + mt * 16 + (l & 7) + ((l >> 3) & 1) * 8;
                int col = kc * 64 + ks * 16 + (l >> 4) * 8;
                ldsm_x4(af[mt], A_s + row * APITCH + col);
            }
            uint32_t bfr[8][2];
#pragma unroll
            for (int np = 0; np < 4; np++) {
                int row = wn * 64 + np * 16 + (l & 7) + (l >> 4) * 8;
                int col = ks * 16 + ((l >> 3) & 1) * 8;
                uint32_t r4[4];
                ldsm_x4(r4, B_s + row * BPITCH + col);
                bfr[2 * np][0] = r4[0]; bfr[2 * np][1] = r4[1];
                bfr[2 * np + 1][0] = r4[2]; bfr[2 * np + 1][1] = r4[3];
            }
#pragma unroll
            for (int mt = 0; mt < 2; mt++)
#pragma unroll
                for (int nt = 0; nt < 8; nt++)
                    mma16816(cf[mt][nt], af[mt], bfr[nt]);
        }
    }
    __syncthreads();  // all warps done with B_s

    // store M fragments (fp32 -> bf16)
#pragma unroll
    for (int mt = 0; mt < 2; mt++)
#pragma unroll
        for (int nt = 0; nt < 8; nt++) {
            int row = wm * 32 + mt * 16 + lq;
            int colb = wn * 64 + nt * 8 + 2 * lr;
            size_t d0 = (size_t)(bx * 64 + row) * DIM + colb;
            *(__nv_bfloat162*)(g_M[n] + d0)           = __floats2bfloat162_rn(cf[mt][nt][0], cf[mt][nt][1]);
            *(__nv_bfloat162*)(g_M[n] + d0 + 8 * DIM) = __floats2bfloat162_rn(cf[mt][nt][2], cf[mt][nt][3]);
        }

    // bias: c[d] = Wo[d,:] @ bv + bo[d], using bf16 A_s copy (biases typically 0)
    {
        int row = tid & 63, part = tid >> 6;
        float s = 0.f;
#pragma unroll 8
        for (int j = 0; j < 64; j++) {
            int jj = part * 64 + j;
            s += __bfloat162float(A_s[row * APITCH + jj]) * bv_s[jj];
        }
        bred[part * 64 + row] = s;
        __syncthreads();
        if (tid < 64) {
            float c = bred[tid] + bred[64 + tid] + bred[128 + tid] + bred[192 + tid] + bo[tid];
            g_c[n][bx * 64 + tid] = c;
        }
    }
}

// ------------------------------------------------------------------
// main fused kernel: 64 rows/CTA, 256 threads (8 warps, 2Mx4N),
// cp.async double-buffered B, fragment-resident gated epilogue.
// ------------------------------------------------------------------
__global__ __launch_bounds__(256, 1)
void fused_main_kernel(const float* __restrict__ x,
                       const float* __restrict__ cross_ln_g, const float* __restrict__ cross_ln_b,
                       const float* __restrict__ gate_ln_g, const float* __restrict__ gate_ln_b,
                       const float* __restrict__ gate_W, const float* __restrict__ gate_b,
                       const float* __restrict__ final_ln_g, const float* __restrict__ final_ln_b,
                       const int* __restrict__ modal_idx, float* __restrict__ out) {
    extern __shared__ char sm[];
    float* q_s = (float*)(sm + SM_Q);                    // [64][QPITCH]
    __nv_bfloat16* A_s = (__nv_bfloat16*)(sm + SM_AT);   // [64][APITCH]
    __nv_bfloat16* B_s = (__nv_bfloat16*)(sm + SM_B);    // [2][256][BPITCH]
    float* gw_s = (float*)(sm + SM_GW);                  // gate_W 1280, ln_g 256, ln_b 256
    float* gates_s = (float*)(sm + SM_GA);               // [64][8]
    float* red_s = (float*)(sm + SM_RED);                // [64][8]
    float2* stat_s = (float2*)(sm + SM_ST);              // [64]

    const int tid = threadIdx.x;
    const int w = tid >> 5, l = tid & 31;
    const int wm = w & 1, wn = w >> 1;
    const int lq = l >> 2, lr = l & 3;
    const int mi = *modal_idx;
    const int r0 = blockIdx.x * TB;

    // prefetch B chunk 0 immediately (hides q load + gates)
    {
        const __nv_bfloat16* src = g_M[0];
#pragma unroll
        for (int i = 0; i < 8; i++) {
            int e = tid + i * 256, row = e >> 3, seg = e & 7;
            cp_async16(B_s + row * BPITCH + seg * 8, src + row * DIM + seg * 8);
        }
        cp_commit();
    }

    // gate constants + q tile
    for (int i = tid; i < 1792; i += 256)
        gw_s[i] = (i < 1280) ? gate_W[i] : (i < 1536 ? gate_ln_g[i - 1280] : gate_ln_b[i - 1536]);
#pragma unroll
    for (int i = 0; i < 16; i++) {
        int e = tid + i * 256, r = e >> 6, c4 = (e & 63) << 2;
        *(float4*)(q_s + r * QPITCH + c4) =
            *(const float4*)(x + (size_t)(r0 + r) * (NMOD * DIM) + mi * DIM + c4);
    }
    __syncthreads();

    // ---- gates: softmax(LN(q) @ gate_W^T + gate_b), warp per 8 rows ----
    {
        float gb[5];
#pragma unroll
        for (int n = 0; n < 5; n++) gb[n] = gate_b[n];
#pragma unroll 1
        for (int ri = 0; ri < 8; ri++) {
            int r = w * 8 + ri;
            float qv[8], sum = 0.f, sq = 0.f;
#pragma unroll
            for (int j = 0; j < 8; j++) {
                qv[j] = q_s[r * QPITCH + l + 32 * j];
                sum += qv[j]; sq += qv[j] * qv[j];
            }
            sum = warp_sum(sum); sq = warp_sum(sq);
            float m = sum * (1.f / DIM);
            float rs = rsqrtf(fmaxf(sq * (1.f / DIM) - m * m, 0.f) + 1e-5f);
            float lnv[8];
#pragma unroll
            for (int j = 0; j < 8; j++) {
                int c = l + 32 * j;
                lnv[j] = (qv[j] - m) * rs * gw_s[1280 + c] + gw_s[1536 + c];
            }
            float lg[5];
#pragma unroll
            for (int n = 0; n < 5; n++) {
                float s = 0.f;
#pragma unroll
                for (int j = 0; j < 8; j++) s += lnv[j] * gw_s[n * DIM + l + 32 * j];
                lg[n] = warp_sum(s) + gb[n];
            }
            float mx = lg[0];
#pragma unroll
            for (int n = 1; n < 5; n++) mx = fmaxf(mx, lg[n]);
            float es = 0.f;
#pragma unroll
            for (int n = 0; n < 5; n++) { lg[n] = expf(lg[n] - mx); es += lg[n]; }
            if (l == 0) {
                float inv = 1.f / es;
#pragma unroll
                for (int n = 0; n < 5; n++) gates_s[r * 8 + n] = lg[n] * inv;
            }
        }
    }

    float acc[2][8][4];

#pragma unroll 1
    for (int n = 0; n < NMOD; n++) {
        const int mod = (n == 0) ? mi : (((n - 1) < mi) ? (n - 1) : n);

        // A tile (bf16): from q_s for self, from x for cross
        if (n == 0) {
#pragma unroll
            for (int i = 0; i < 16; i++) {
                int e = tid + i * 256, r = e >> 6, c4 = (e & 63) << 2;
                float4 v = *(const float4*)(q_s + r * QPITCH + c4);
                __nv_bfloat16* dst = A_s + r * APITCH + c4;
                *(__nv_bfloat162*)(dst)     = __floats2bfloat162_rn(v.x, v.y);
                *(__nv_bfloat162*)(dst + 2) = __floats2bfloat162_rn(v.z, v.w);
            }
        } else {
#pragma unroll
            for (int i = 0; i < 16; i++) {
                int e = tid + i * 256, r = e >> 6, c4 = (e & 63) << 2;
                float4 v = *(const float4*)(x + (size_t)(r0 + r) * (NMOD * DIM) + mod * DIM + c4);
                __nv_bfloat16* dst = A_s + r * APITCH + c4;
                *(__nv_bfloat162*)(dst)     = __floats2bfloat162_rn(v.x, v.y);
                *(__nv_bfloat162*)(dst + 2) = __floats2bfloat162_rn(v.z, v.w);
            }
        }

        float cf[2][8][4];
#pragma unroll
        for (int mt = 0; mt < 2; mt++)
#pragma unroll
            for (int nt = 0; nt < 8; nt++)
#pragma unroll
                for (int i = 0; i < 4; i++) cf[mt][nt][i] = 0.f;

#pragma unroll 1
        for (int kc = 0; kc < 4; kc++) {
            int c = n * 4 + kc;
            cp_wait_all();
            __syncthreads();  // chunk c visible; prev chunk's buffer free; A_s visible
            if (c + 1 < 20) {
                int n2 = (c + 1) >> 2, kc2 = (c + 1) & 3;
                const __nv_bfloat16* src = g_M[n2] + kc2 * 64;
                __nv_bfloat16* dst = B_s + ((c + 1) & 1) * (DIM * BPITCH);
#pragma unroll
                for (int i = 0; i < 8; i++) {
                    int e = tid + i * 256, row = e >> 3, seg = e & 7;
                    cp_async16(dst + row * BPITCH + seg * 8, src + row * DIM + seg * 8);
                }
                cp_commit();
            }
            const __nv_bfloat16* Bc = B_s + (c & 1) * (DIM * BPITCH);
#pragma unroll
            for (int ks = 0; ks < 4; ks++) {
                uint32_t af[2][4];
#pragma unroll
                for (int mt = 0; mt < 2; mt++) {
                    int row = wm * 32 + mt * 16 + (l & 7) + ((l >> 3) & 1) * 8;
                    int col = kc * 64 + ks * 16 + (l >> 4) * 8;
                    ldsm_x4(af[mt], A_s + row * APITCH + col);
                }
                uint32_t bfr[8][2];
#pragma unroll
                for (int np = 0; np < 4; np++) {
                    int row = wn * 64 + np * 16 + (l & 7) + (l >> 4) * 8;
                    int col = ks * 16 + ((l >> 3) & 1) * 8;
                    uint32_t r4[4];
                    ldsm_x4(r4, Bc + row * BPITCH + col);
                    bfr[2 * np][0] = r4[0]; bfr[2 * np][1] = r4[1];
                    bfr[2 * np + 1][0] = r4[2]; bfr[2 * np + 1][1] = r4[3];
                }
#pragma unroll
                for (int mt = 0; mt < 2; mt++)
#pragma unroll
                    for (int nt = 0; nt < 8; nt++)
                        mma16816(cf[mt][nt], af[mt], bfr[nt]);
            }
        }

        // ---- epilogue in fragment layout ----
        float cfr[8][2];
        {
            const float* cv = g_c[n];
#pragma unroll
            for (int nt = 0; nt < 8; nt++) {
                float2 t = *(const float2*)(cv + wn * 64 + nt * 8 + 2 * lr);
                cfr[nt][0] = t.x; cfr[nt][1] = t.y;
            }
        }

        if (n == 0) {
#pragma unroll
            for (int mt = 0; mt < 2; mt++)
#pragma unroll
                for (int half = 0; half < 2; half++) {
                    int row = wm * 32 + mt * 16 + lq + half * 8;
                    float g0 = gates_s[row * 8 + 0];
#pragma unroll
                    for (int nt = 0; nt < 8; nt++) {
                        acc[mt][nt][2 * half + 0] = g0 * (cf[mt][nt][2 * half + 0] + cfr[nt][0]);
                        acc[mt][nt][2 * half + 1] = g0 * (cf[mt][nt][2 * half + 1] + cfr[nt][1]);
                    }
                }
            __syncthreads();  // all warps past mma before next branch rewrites A_s
        } else {
            float gmf[8][2], btf[8][2];
            {
                const float* lng = cross_ln_g + (n - 1) * DIM;
                const float* lnb = cross_ln_b + (n - 1) * DIM;
#pragma unroll
                for (int nt = 0; nt < 8; nt++) {
                    float2 tg = *(const float2*)(lng + wn * 64 + nt * 8 + 2 * lr);
                    float2 tb = *(const float2*)(lnb + wn * 64 + nt * 8 + 2 * lr);
                    gmf[nt][0] = tg.x; gmf[nt][1] = tg.y;
                    btf[nt][0] = tb.x; btf[nt][1] = tb.y;
                }
            }
            float sums[2][2], sqs[2][2];
#pragma unroll
            for (int mt = 0; mt < 2; mt++)
#pragma unroll
                for (int half = 0; half < 2; half++) {
                    int row = wm * 32 + mt * 16 + lq + half * 8;
                    float s = 0.f, ss = 0.f;
#pragma unroll
                    for (int nt = 0; nt < 8; nt++) {
                        float2 q2 = *(const float2*)(q_s + row * QPITCH + wn * 64 + nt * 8 + 2 * lr);
                        float t0 = q2.x + cf[mt][nt][2 * half + 0] + cfr[nt][0];
                        float t1 = q2.y + cf[mt][nt][2 * half + 1] + cfr[nt][1];
                        cf[mt][nt][2 * half + 0] = t0;
                        cf[mt][nt][2 * half + 1] = t1;
                        s += t0 + t1; ss += t0 * t0 + t1 * t1;
                    }
                    s += __shfl_xor_sync(0xffffffffu, s, 1);
                    s += __shfl_xor_sync(0xffffffffu, s, 2);
                    ss += __shfl_xor_sync(0xffffffffu, ss, 1);
                    ss += __shfl_xor_sync(0xffffffffu, ss, 2);
                    sums[mt][half] = s; sqs[mt][half] = ss;
                }
            if (lr == 0) {
#pragma unroll
                for (int mt = 0; mt < 2; mt++)
#pragma unroll
                    for (int half = 0; half < 2; half++) {
                        int row = wm * 32 + mt * 16 + lq + half * 8;
                        red_s[row * 8 + wn * 2 + 0] = sums[mt][half];
                        red_s[row * 8 + wn * 2 + 1] = sqs[mt][half];
                    }
            }
            __syncthreads();
            if (tid < 64) {
                float s = red_s[tid * 8 + 0] + red_s[tid * 8 + 2] + red_s[tid * 8 + 4] + red_s[tid * 8 + 6];
                float ss = red_s[tid * 8 + 1] + red_s[tid * 8 + 3] + red_s[tid * 8 + 5] + red_s[tid * 8 + 7];
                float m = s * (1.f / DIM);
                float var = fmaxf(ss * (1.f / DIM) - m * m, 0.f);
                stat_s[tid] = make_float2(m, rsqrtf(var + 1e-5f));
            }
            __syncthreads();
#pragma unroll
            for (int mt = 0; mt < 2; mt++)
#pragma unroll
                for (int half = 0; half < 2; half++) {
                    int row = wm * 32 + mt * 16 + lq + half * 8;
                    float2 st = stat_s[row];
                    float gn = gates_s[row * 8 + n];
#pragma unroll
                    for (int nt = 0; nt < 8; nt++) {
                        acc[mt][nt][2 * half + 0] +=
                            gn * ((cf[mt][nt][2 * half + 0] - st.x) * st.y * gmf[nt][0] + btf[nt][0]);
                        acc[mt][nt][2 * half + 1] +=
                            gn * ((cf[mt][nt][2 * half + 1] - st.x) * st.y * gmf[nt][1] + btf[nt][1]);
                    }
                }
        }
    }

    // ---- final LN(q + combined) in fragment layout, store ----
    {
        float fgf[8][2], fbf[8][2];
#pragma unroll
        for (int nt = 0; nt < 8; nt++) {
            float2 tg = *(const float2*)(final_ln_g + wn * 64 + nt * 8 + 2 * lr);
            float2 tb = *(const float2*)(final_ln_b + wn * 64 + nt * 8 + 2 * lr);
            fgf[nt][0] = tg.x; fgf[nt][1] = tg.y;
            fbf[nt][0] = tb.x; fbf[nt][1] = tb.y;
        }
        float sums[2][2], sqs[2][2];
#pragma unroll
        for (int mt = 0; mt < 2; mt++)
#pragma unroll
            for (int half = 0; half < 2; half++) {
                int row = wm * 32 + mt * 16 + lq + half * 8;
                float s = 0.f, ss = 0.f;
#pragma unroll
                for (int nt = 0; nt < 8; nt++) {
                    float2 q2 = *(const float2*)(q_s + row * QPITCH + wn * 64 + nt * 8 + 2 * lr);
                    float t0 = q2.x + acc[mt][nt][2 * half + 0];
                    float t1 = q2.y + acc[mt][nt][2 * half + 1];
                    acc[mt][nt][2 * half + 0] = t0;
                    acc[mt][nt][2 * half + 1] = t1;
                    s += t0 + t1; ss += t0 * t0 + t1 * t1;
                }
                s += __shfl_xor_sync(0xffffffffu, s, 1);
                s += __shfl_xor_sync(0xffffffffu, s, 2);
                ss += __shfl_xor_sync(0xffffffffu, ss, 1);
                ss += __shfl_xor_sync(0xffffffffu, ss, 2);
                sums[mt][half] = s; sqs[mt][half] = ss;
            }
        __syncthreads();  // red_s free from last branch
        if (lr == 0) {
#pragma unroll
            for (int mt = 0; mt < 2; mt++)
#pragma unroll
                for (int half = 0; half < 2; half++) {
                    int row = wm * 32 + mt * 16 + lq + half * 8;
                    red_s[row * 8 + wn * 2 + 0] = sums[mt][half];
                    red_s[row * 8 + wn * 2 + 1] = sqs[mt][half];
                }
        }
        __syncthreads();
        if (tid < 64) {
            float s = red_s[tid * 8 + 0] + red_s[tid * 8 + 2] + red_s[tid * 8 + 4] + red_s[tid * 8 + 6];
            float ss = red_s[tid * 8 + 1] + red_s[tid * 8 + 3] + red_s[tid * 8 + 5] + red_s[tid * 8 + 7];
            float m = s * (1.f / DIM);
            float var = fmaxf(ss * (1.f / DIM) - m * m, 0.f);
            stat_s[tid] = make_float2(m, rsqrtf(var + 1e-5f));
        }
        __syncthreads();
#pragma unroll
        for (int mt = 0; mt < 2; mt++)
#pragma unroll
            for (int half = 0; half < 2; half++) {
                int row = wm * 32 + mt * 16 + lq + half * 8;
                float2 st = stat_s[row];
#pragma unroll
                for (int nt = 0; nt < 8; nt++) {
                    int colb = wn * 64 + nt * 8 + 2 * lr;
                    float o0 = (acc[mt][nt][2 * half + 0] - st.x) * st.y * fgf[nt][0] + fbf[nt][0];
                    float o1 = (acc[mt][nt][2 * half + 1] - st.x) * st.y * fgf[nt][1] + fbf[nt][1];
                    *(float2*)(out + (size_t)(r0 + row) * DIM + colb) = make_float2(o0, o1);
                }
            }
    }
}

// ------------------------------------------------------------------
extern "C" void kernel_launch(void* const* d_in, const int* in_sizes, int n_in,
                              void* d_out, int out_size) {
    (void)in_sizes; (void)n_in; (void)out_size;
    const float* x          = (const float*)d_in[0];
    const float* self_Wi    = (const float*)d_in[1];
    const float* self_bi    = (const float*)d_in[2];
    const float* self_Wo    = (const float*)d_in[3];
    const float* self_bo    = (const float*)d_in[4];
    const float* cross_Wi   = (const float*)d_in[5];
    const float* cross_bi   = (const float*)d_in[6];
    const float* cross_Wo   = (const float*)d_in[7];
    const float* cross_bo   = (const float*)d_in[8];
    const float* cross_ln_g = (const float*)d_in[9];
    const float* cross_ln_b = (const float*)d_in[10];
    const float* gate_ln_g  = (const float*)d_in[11];
    const float* gate_ln_b  = (const float*)d_in[12];
    const float* gate_W     = (const float*)d_in[13];
    const float* gate_b     = (const float*)d_in[14];
    const float* final_ln_g = (const float*)d_in[15];
    const float* final_ln_b = (const float*)d_in[16];
    const int*   modal_idx  = (const int*)d_in[17];
    float* out = (float*)d_out;

    static bool attr_set = false;
    if (!attr_set) {
        cudaFuncSetAttribute(fused_main_kernel,
                             cudaFuncAttributeMaxDynamicSharedMemorySize, SMEM_TOTAL);
        cudaFuncSetAttribute(fuse_weights_kernel,
                             cudaFuncAttributeMaxDynamicSharedMemorySize, 72704);
        attr_set = true;
    }

    fuse_weights_kernel<<<dim3(4, 5), 256, 72704>>>(self_Wi, self_bi, self_Wo, self_bo,
                                                    cross_Wi, cross_bi, cross_Wo, cross_bo);
    fused_main_kernel<<<NROWS / TB, 256, SMEM_TOTAL>>>(
        x, cross_ln_g, cross_ln_b, gate_ln_g, gate_ln_b,
        gate_W, gate_b, final_ln_g, final_ln_b, modal_idx, out);
}